// round 12
// baseline (speedup 1.0000x reference)
#include <cuda_runtime.h>
#include <cuda_fp16.h>

#define N_NODES 100000
#define N_EDGES 1600000
#define SCAN_BLOCKS 98    // ceil(100000/1024)
#define GEMM_BLOCKS 782   // ceil(100000/128)

// GEMM smem (fp32 words): double-buffered K-chunks, 128 rows/block
#define SA_STRIDE 36         // 32 + 4 pad  -> frag bank (4*qid + t4) conflict-free
#define SW_STRIDE 136        // 128 + 8 pad -> frag bank (8*t4 + qid) conflict-free
#define SA_BUF (128 * SA_STRIDE)          // 4608 words per buffer
#define SW_BUF (32 * SW_STRIDE)           // 4352 words per buffer
#define GEMM_SMEM ((2 * SA_BUF + 2 * SW_BUF) * 4)   // 71680 B -> 2 blocks/SM

typedef unsigned long long ull;

// ---------------- scratch (static __device__ allocations; no cudaMalloc) ----
__device__ __half g_y16[(size_t)N_NODES * 128];  // (A@W)*dinv buffer (fp16)
__device__ float  g_h[(size_t)N_NODES * 128];    // post-aggregate hidden buffer
__device__ int    g_cnt[N_NODES];                // zero-initialized; re-zeroed by k_fill
__device__ int    g_rowptr[N_NODES + 1];
__device__ int    g_cursor[N_NODES];
__device__ float  g_dinv[N_NODES];
__device__ int    g_csr[N_EDGES];
__device__ ull    g_scan_pkt[SCAN_BLOCKS];       // (flag<<32)|value; reset by k_fill

// ---------------- helpers ---------------------------------------------------
__device__ __forceinline__ unsigned to_tf32(float x) {
    unsigned r;
    asm("cvt.rna.tf32.f32 %0, %1;" : "=r"(r) : "f"(x));
    return r;
}

__device__ __forceinline__ void mma_tf32(
    float& d0, float& d1, float& d2, float& d3,
    unsigned a0, unsigned a1, unsigned a2, unsigned a3,
    unsigned b0, unsigned b1)
{
    asm("mma.sync.aligned.m16n8k8.row.col.f32.tf32.tf32.f32 "
        "{%0,%1,%2,%3}, {%4,%5,%6,%7}, {%8,%9}, {%0,%1,%2,%3};"
        : "+f"(d0), "+f"(d1), "+f"(d2), "+f"(d3)
        : "r"(a0), "r"(a1), "r"(a2), "r"(a3), "r"(b0), "r"(b1));
}

__device__ __forceinline__ void cp_async16(void* smem_dst, const void* gsrc) {
    unsigned saddr = (unsigned)__cvta_generic_to_shared(smem_dst);
    asm volatile("cp.async.ca.shared.global [%0], [%1], 16;"
                 :: "r"(saddr), "l"(gsrc));
}
__device__ __forceinline__ void cp_commit() {
    asm volatile("cp.async.commit_group;");
}
template <int N>
__device__ __forceinline__ void cp_wait() {
    asm volatile("cp.async.wait_group %0;" :: "n"(N));
}

__device__ __forceinline__ void edge_fetch(const int* __restrict__ ei, int e,
                                           int& src, int& dst, int is64) {
    if (is64) {
        src = ei[2 * e];
        dst = ei[2 * (N_EDGES + e)];
    } else {
        src = ei[e];
        dst = ei[N_EDGES + e];
    }
}

// detect int64-vs-int32 edge layout, broadcast through smem (per block)
__device__ __forceinline__ int block_is64(const int* __restrict__ ei) {
    __shared__ int s_is64;
    if (threadIdx.x == 0) {
        int acc = 0;
        for (int j = 0; j < 64; j++) acc |= ei[2 * j + 1];
        s_is64 = (acc == 0) ? 1 : 0;
    }
    __syncthreads();
    return s_is64;
}

// ---------------- histogram --------------------------------------------------
__global__ void k_hist(const int* __restrict__ ei) {
    const int is64 = block_is64(ei);
    int e = blockIdx.x * blockDim.x + threadIdx.x;
    if (e < N_EDGES) {
        int src, dst;
        edge_fetch(ei, e, src, dst, is64);
        if ((unsigned)dst < N_NODES) atomicAdd(&g_cnt[dst], 1);
    }
}

// ---------------- single-pass scan (decoupled lookback) + rowptr/dinv --------
__global__ void __launch_bounds__(1024) k_scan() {
    __shared__ int sm[1024];
    __shared__ int s_prefix;
    const int b = blockIdx.x;
    const int i = b * 1024 + threadIdx.x;
    const int v = (i < N_NODES) ? g_cnt[i] : 0;
    sm[threadIdx.x] = v;
    __syncthreads();
#pragma unroll
    for (int off = 1; off < 1024; off <<= 1) {
        int t = (threadIdx.x >= off) ? sm[threadIdx.x - off] : 0;
        __syncthreads();
        sm[threadIdx.x] += t;
        __syncthreads();
    }
    const int incl = sm[threadIdx.x];

    if (threadIdx.x == 0) {
        const int total = sm[1023];
        if (b == 0) {
            atomicExch(&g_scan_pkt[0], (2ull << 32) | (unsigned)total);
            s_prefix = 0;
        } else {
            atomicExch(&g_scan_pkt[b], (1ull << 32) | (unsigned)total);
            int pfx = 0;
            int j = b - 1;
            while (true) {
                ull w;
                do { w = *(volatile ull*)&g_scan_pkt[j]; } while ((w >> 32) == 0);
                pfx += (int)(unsigned)w;
                if ((w >> 32) == 2ull) break;
                j--;
            }
            atomicExch(&g_scan_pkt[b], (2ull << 32) | (unsigned)(pfx + total));
            s_prefix = pfx;
        }
    }
    __syncthreads();
    const int pfx = s_prefix;
    if (i < N_NODES) {
        const int rp = pfx + incl - v;
        g_rowptr[i] = rp;
        g_cursor[i] = rp;
        g_dinv[i] = rsqrtf((float)(g_cnt[i] + 1));  // +1 self-loop
    }
    if (i == 0) g_rowptr[N_NODES] = N_EDGES;
}

// ---------------- CSR fill; also restores g_cnt / g_scan_pkt for next replay -
__global__ void k_fill(const int* __restrict__ ei) {
    const int is64 = block_is64(ei);
    int e = blockIdx.x * blockDim.x + threadIdx.x;
    if (e < N_EDGES) {
        int src, dst;
        edge_fetch(ei, e, src, dst, is64);
        if ((unsigned)dst < N_NODES && (unsigned)src < N_NODES) {
            int pos = atomicAdd(&g_cursor[dst], 1);
            g_csr[pos] = src;
        }
    }
    // reset state for next graph replay (cnt consumed by scan; pkt by scan)
    if (e < N_NODES) g_cnt[e] = 0;
    if (e < SCAN_BLOCKS) g_scan_pkt[e] = 0ull;
}

// ---------------- cp.async double-buffered tf32 GEMM ------------------------
// Block: 128 rows x 128 cols, 256 threads (8 warps of 32x64 tile), 2 blocks/SM.
// K split into 4 chunks of 32, double-buffered via cp.async; rna tf32 cvts.
template <int SRC>
__global__ void __launch_bounds__(256, 2) k_gemm_cp(
    const float* __restrict__ Ain, const float* __restrict__ W)
{
    const float* __restrict__ A = (SRC == 0) ? Ain : (const float*)g_h;

    extern __shared__ float smem_f[];
    float* sA = smem_f;                 // [2][128][SA_STRIDE]
    float* sW = smem_f + 2 * SA_BUF;    // [2][32][SW_STRIDE]

    const int t = threadIdx.x;
    const int rb = blockIdx.x * 128;

    auto stage = [&](int chunk, int buf) {
        // A: 128 rows x 32 floats = 1024 x 16B ops, 4/thread
#pragma unroll
        for (int p = 0; p < 4; p++) {
            int idx = p * 256 + t;
            int row = idx >> 3, seg = idx & 7;
            int g = rb + row; if (g >= N_NODES) g = N_NODES - 1;
            cp_async16(sA + buf * SA_BUF + row * SA_STRIDE + seg * 4,
                       A + (size_t)g * 128 + chunk * 32 + seg * 4);
        }
        // W: 32 rows x 128 floats = 1024 x 16B ops, 4/thread
#pragma unroll
        for (int p = 0; p < 4; p++) {
            int idx = p * 256 + t;
            int row = idx >> 5, seg = idx & 31;
            cp_async16(sW + buf * SW_BUF + row * SW_STRIDE + seg * 4,
                       W + (size_t)(chunk * 32 + row) * 128 + seg * 4);
        }
        cp_commit();
    };

    const int lane = t & 31;
    const int warp = t >> 5;
    const int m0w = (warp >> 1) * 32;
    const int c0w = (warp & 1) * 64;
    const int qid = lane >> 2;
    const int t4 = lane & 3;

    float d[2][8][4];
#pragma unroll
    for (int mt = 0; mt < 2; mt++)
#pragma unroll
        for (int nt = 0; nt < 8; nt++)
#pragma unroll
            for (int i = 0; i < 4; i++) d[mt][nt][i] = 0.f;

    stage(0, 0);

#pragma unroll
    for (int c = 0; c < 4; c++) {
        if (c < 3) stage(c + 1, (c + 1) & 1);
        if (c < 3) cp_wait<1>(); else cp_wait<0>();
        __syncthreads();

        const float* cA = sA + (c & 1) * SA_BUF;
        const float* cW = sW + (c & 1) * SW_BUF;
#pragma unroll
        for (int it = 0; it < 4; it++) {
            const int k = it * 8;
            unsigned a[2][4];
#pragma unroll
            for (int mt = 0; mt < 2; mt++) {
                const int base = (m0w + mt * 16 + qid) * SA_STRIDE + k + t4;
                a[mt][0] = to_tf32(cA[base]);
                a[mt][1] = to_tf32(cA[base + 8 * SA_STRIDE]);
                a[mt][2] = to_tf32(cA[base + 4]);
                a[mt][3] = to_tf32(cA[base + 8 * SA_STRIDE + 4]);
            }
#pragma unroll
            for (int nt = 0; nt < 8; nt++) {
                const int wb = (k + t4) * SW_STRIDE + c0w + nt * 8 + qid;
                unsigned b0 = to_tf32(cW[wb]);
                unsigned b1 = to_tf32(cW[wb + 4 * SW_STRIDE]);
                mma_tf32(d[0][nt][0], d[0][nt][1], d[0][nt][2], d[0][nt][3],
                         a[0][0], a[0][1], a[0][2], a[0][3], b0, b1);
                mma_tf32(d[1][nt][0], d[1][nt][1], d[1][nt][2], d[1][nt][3],
                         a[1][0], a[1][1], a[1][2], a[1][3], b0, b1);
            }
        }
        __syncthreads();
    }

#pragma unroll
    for (int mt = 0; mt < 2; mt++) {
        const int row = rb + m0w + mt * 16 + qid;
        if (row < N_NODES) {
            const float s0 = g_dinv[row];
#pragma unroll
            for (int nt = 0; nt < 8; nt++) {
                const int col = c0w + nt * 8 + t4 * 2;
                *(__half2*)(g_y16 + (size_t)row * 128 + col) =
                    __floats2half2_rn(d[mt][nt][0] * s0, d[mt][nt][1] * s0);
            }
        }
        if (row + 8 < N_NODES) {
            const float s1 = g_dinv[row + 8];
#pragma unroll
            for (int nt = 0; nt < 8; nt++) {
                const int col = c0w + nt * 8 + t4 * 2;
                *(__half2*)(g_y16 + (size_t)(row + 8) * 128 + col) =
                    __floats2half2_rn(d[mt][nt][2] * s1, d[mt][nt][3] * s1);
            }
        }
    }
}

// ---------------- cp.async FC head ------------------------------------------
// Same skeleton, 128 rows; K=144 = 4x32 chunks (g_h) + 16 tail (action).
// Epilogue: relu(+b1), dot fc2 over own 64 cols, quad-reduce, cross-warp-pair
// combine via smem scratch. q = ... + b2.
__global__ void __launch_bounds__(256, 2) k_fc_cp(
    const float* __restrict__ act, const float* __restrict__ W,
    const float* __restrict__ bias, const float* __restrict__ w2,
    const float* __restrict__ w2b, float* __restrict__ out)
{
    extern __shared__ float smem_f[];
    float* sA = smem_f;                 // [2][128][SA_STRIDE]
    float* sW = smem_f + 2 * SA_BUF;    // [2][32][SW_STRIDE]

    const int t = threadIdx.x;
    const int rb = blockIdx.x * 128;

    auto stage_main = [&](int chunk, int buf) {
#pragma unroll
        for (int p = 0; p < 4; p++) {
            int idx = p * 256 + t;
            int row = idx >> 3, seg = idx & 7;
            int g = rb + row; if (g >= N_NODES) g = N_NODES - 1;
            cp_async16(sA + buf * SA_BUF + row * SA_STRIDE + seg * 4,
                       g_h + (size_t)g * 128 + chunk * 32 + seg * 4);
        }
#pragma unroll
        for (int p = 0; p < 4; p++) {
            int idx = p * 256 + t;
            int row = idx >> 5, seg = idx & 31;
            cp_async16(sW + buf * SW_BUF + row * SW_STRIDE + seg * 4,
                       W + (size_t)(chunk * 32 + row) * 128 + seg * 4);
        }
        cp_commit();
    };
    auto stage_tail = [&](int buf) {
        // action: 128 rows x 16 floats = 512 x 16B ops, 2/thread
#pragma unroll
        for (int p = 0; p < 2; p++) {
            int idx = p * 256 + t;
            int row = idx >> 2, seg = idx & 3;
            int g = rb + row; if (g >= N_NODES) g = N_NODES - 1;
            cp_async16(sA + buf * SA_BUF + row * SA_STRIDE + seg * 4,
                       act + (size_t)g * 16 + seg * 4);
        }
        // W rows 128..143 x 128 = 512 x 16B ops, 2/thread
#pragma unroll
        for (int p = 0; p < 2; p++) {
            int idx = p * 256 + t;
            int row = idx >> 5, seg = idx & 31;
            cp_async16(sW + buf * SW_BUF + row * SW_STRIDE + seg * 4,
                       W + (size_t)(128 + row) * 128 + seg * 4);
        }
        cp_commit();
    };

    const int lane = t & 31;
    const int warp = t >> 5;
    const int m0w = (warp >> 1) * 32;
    const int c0w = (warp & 1) * 64;
    const int qid = lane >> 2;
    const int t4 = lane & 3;

    float d[2][8][4];
#pragma unroll
    for (int mt = 0; mt < 2; mt++)
#pragma unroll
        for (int nt = 0; nt < 8; nt++)
#pragma unroll
            for (int i = 0; i < 4; i++) d[mt][nt][i] = 0.f;

    stage_main(0, 0);

#pragma unroll
    for (int c = 0; c < 5; c++) {
        if (c < 4) {
            if (c + 1 < 4) stage_main(c + 1, (c + 1) & 1);
            else stage_tail((c + 1) & 1);
            cp_wait<1>();
        } else {
            cp_wait<0>();
        }
        __syncthreads();

        const float* cA = sA + (c & 1) * SA_BUF;
        const float* cW = sW + (c & 1) * SW_BUF;
        const int iters = (c < 4) ? 4 : 2;
#pragma unroll
        for (int it = 0; it < 4; it++) {
            if (it >= iters) break;
            const int k = it * 8;
            unsigned a[2][4];
#pragma unroll
            for (int mt = 0; mt < 2; mt++) {
                const int base = (m0w + mt * 16 + qid) * SA_STRIDE + k + t4;
                a[mt][0] = to_tf32(cA[base]);
                a[mt][1] = to_tf32(cA[base + 8 * SA_STRIDE]);
                a[mt][2] = to_tf32(cA[base + 4]);
                a[mt][3] = to_tf32(cA[base + 8 * SA_STRIDE + 4]);
            }
#pragma unroll
            for (int nt = 0; nt < 8; nt++) {
                const int wb = (k + t4) * SW_STRIDE + c0w + nt * 8 + qid;
                unsigned b0 = to_tf32(cW[wb]);
                unsigned b1 = to_tf32(cW[wb + 4 * SW_STRIDE]);
                mma_tf32(d[0][nt][0], d[0][nt][1], d[0][nt][2], d[0][nt][3],
                         a[0][0], a[0][1], a[0][2], a[0][3], b0, b1);
                mma_tf32(d[1][nt][0], d[1][nt][1], d[1][nt][2], d[1][nt][3],
                         a[1][0], a[1][1], a[1][2], a[1][3], b0, b1);
            }
        }
        __syncthreads();
    }

    // epilogue: relu(+bias) . fc2 over this warp's 64 cols
    float p[2][2];
    p[0][0] = p[0][1] = p[1][0] = p[1][1] = 0.f;
#pragma unroll
    for (int mt = 0; mt < 2; mt++)
#pragma unroll
        for (int nt = 0; nt < 8; nt++) {
            const int col = c0w + nt * 8 + t4 * 2;
            float2 bv = *(const float2*)(bias + col);
            float2 wv = *(const float2*)(w2 + col);
            p[mt][0] += fmaxf(d[mt][nt][0] + bv.x, 0.f) * wv.x
                      + fmaxf(d[mt][nt][1] + bv.y, 0.f) * wv.y;
            p[mt][1] += fmaxf(d[mt][nt][2] + bv.x, 0.f) * wv.x
                      + fmaxf(d[mt][nt][3] + bv.y, 0.f) * wv.y;
        }
#pragma unroll
    for (int mt = 0; mt < 2; mt++)
#pragma unroll
        for (int h = 0; h < 2; h++) {
            p[mt][h] += __shfl_xor_sync(0xFFFFFFFFu, p[mt][h], 1);
            p[mt][h] += __shfl_xor_sync(0xFFFFFFFFu, p[mt][h], 2);
        }

    // cross-warp-pair combine via smem scratch (safe after the final barrier)
    float* scr = smem_f;   // 128 floats
    if (c0w == 0 && t4 == 0) {
#pragma unroll
        for (int mt = 0; mt < 2; mt++) {
            scr[m0w + mt * 16 + qid] = p[mt][0];
            scr[m0w + mt * 16 + qid + 8] = p[mt][1];
        }
    }
    __syncthreads();
    if (c0w == 64 && t4 == 0) {
        const float ob = __ldg(w2b);
#pragma unroll
        for (int mt = 0; mt < 2; mt++) {
            int lr = m0w + mt * 16 + qid;
            int grow = rb + lr;
            if (grow < N_NODES) out[grow] = p[mt][0] + scr[lr] + ob;
            if (grow + 8 < N_NODES) out[grow + 8] = p[mt][1] + scr[lr + 8] + ob;
        }
    }
}

// ---------------- gather-aggregate: one warp per dst row (fp16 y) -----------
__global__ void __launch_bounds__(256) k_aggregate(
    const float* __restrict__ bias)
{
    const int lane = threadIdx.x & 31;
    const int warp = threadIdx.x >> 5;
    const int row = blockIdx.x * 8 + warp;
    if (row >= N_NODES) return;

    const int s = g_rowptr[row];
    const int e = g_rowptr[row + 1];
    const uint2* yv = (const uint2*)g_y16;

    float4 a0, a1, a2, a3;
    {
        uint2 u = __ldg(&yv[(size_t)row * 32 + lane]);
        float2 f0 = __half22float2(*(__half2*)&u.x);
        float2 f1 = __half22float2(*(__half2*)&u.y);
        a0 = make_float4(f0.x, f0.y, f1.x, f1.y);
    }
    a1 = make_float4(0.f, 0.f, 0.f, 0.f);
    a2 = a1; a3 = a1;

    int i = s;
    for (; i + 4 <= e; i += 4) {
        int i0 = g_csr[i + 0];
        int i1 = g_csr[i + 1];
        int i2 = g_csr[i + 2];
        int i3 = g_csr[i + 3];
        uint2 u0 = __ldg(&yv[(size_t)i0 * 32 + lane]);
        uint2 u1 = __ldg(&yv[(size_t)i1 * 32 + lane]);
        uint2 u2 = __ldg(&yv[(size_t)i2 * 32 + lane]);
        uint2 u3 = __ldg(&yv[(size_t)i3 * 32 + lane]);
        float2 f;
        f = __half22float2(*(__half2*)&u0.x); a0.x += f.x; a0.y += f.y;
        f = __half22float2(*(__half2*)&u0.y); a0.z += f.x; a0.w += f.y;
        f = __half22float2(*(__half2*)&u1.x); a1.x += f.x; a1.y += f.y;
        f = __half22float2(*(__half2*)&u1.y); a1.z += f.x; a1.w += f.y;
        f = __half22float2(*(__half2*)&u2.x); a2.x += f.x; a2.y += f.y;
        f = __half22float2(*(__half2*)&u2.y); a2.z += f.x; a2.w += f.y;
        f = __half22float2(*(__half2*)&u3.x); a3.x += f.x; a3.y += f.y;
        f = __half22float2(*(__half2*)&u3.y); a3.z += f.x; a3.w += f.y;
    }
    for (; i < e; i++) {
        int ix = g_csr[i];
        uint2 u = __ldg(&yv[(size_t)ix * 32 + lane]);
        float2 f;
        f = __half22float2(*(__half2*)&u.x); a0.x += f.x; a0.y += f.y;
        f = __half22float2(*(__half2*)&u.y); a0.z += f.x; a0.w += f.y;
    }
    float4 a = make_float4(a0.x + a1.x + a2.x + a3.x,
                           a0.y + a1.y + a2.y + a3.y,
                           a0.z + a1.z + a2.z + a3.z,
                           a0.w + a1.w + a2.w + a3.w);

    const float dv = g_dinv[row];
    float4 b4 = __ldg((const float4*)(bias + lane * 4));
    float4 o = make_float4(fmaxf(a.x * dv + b4.x, 0.f),
                           fmaxf(a.y * dv + b4.y, 0.f),
                           fmaxf(a.z * dv + b4.z, 0.f),
                           fmaxf(a.w * dv + b4.w, 0.f));
    *(float4*)(g_h + (size_t)row * 128 + lane * 4) = o;
}

// ---------------- launch ----------------------------------------------------
extern "C" void kernel_launch(void* const* d_in, const int* in_sizes, int n_in,
                              void* d_out, int out_size)
{
    const float* x      = (const float*)d_in[0];
    const int*   ei     = (const int*)d_in[1];
    const float* action = (const float*)d_in[2];
    const float* g1w    = (const float*)d_in[3];
    const float* g1b    = (const float*)d_in[4];
    const float* g2w    = (const float*)d_in[5];
    const float* g2b    = (const float*)d_in[6];
    const float* f1w    = (const float*)d_in[7];
    const float* f1b    = (const float*)d_in[8];
    const float* f2w    = (const float*)d_in[9];
    const float* f2b    = (const float*)d_in[10];
    float*       q      = (float*)d_out;

    cudaFuncSetAttribute(k_gemm_cp<0>, cudaFuncAttributeMaxDynamicSharedMemorySize, GEMM_SMEM);
    cudaFuncSetAttribute(k_gemm_cp<1>, cudaFuncAttributeMaxDynamicSharedMemorySize, GEMM_SMEM);
    cudaFuncSetAttribute(k_fc_cp,      cudaFuncAttributeMaxDynamicSharedMemorySize, GEMM_SMEM);

    const int agg_grid = (N_NODES + 7) / 8;

    // 8 launches; gemm1 kept at index 3 for the ncu window
    k_hist<<<(N_EDGES + 255) / 256, 256>>>(ei);                     // 0
    k_scan<<<SCAN_BLOCKS, 1024>>>();                                // 1
    k_fill<<<(N_EDGES + 255) / 256, 256>>>(ei);                     // 2
    k_gemm_cp<0><<<GEMM_BLOCKS, 256, GEMM_SMEM>>>(x, g1w);          // 3  <- profiled
    k_aggregate<<<agg_grid, 256>>>(g1b);                            // 4

    k_gemm_cp<1><<<GEMM_BLOCKS, 256, GEMM_SMEM>>>(nullptr, g2w);    // 5
    k_aggregate<<<agg_grid, 256>>>(g2b);                            // 6

    k_fc_cp<<<GEMM_BLOCKS, 256, GEMM_SMEM>>>(action, f1w, f1b, f2w, f2b, q);  // 7
}

// round 15
// speedup vs baseline: 1.6383x; 1.6383x over previous
#include <cuda_runtime.h>
#include <cuda_fp16.h>

#define N_NODES 100000
#define N_EDGES 1600000
#define SCAN_BLOCKS 98    // ceil(100000/1024)
#define GEMM_BLOCKS 391   // ceil(100000/256)

// GEMM smem (fp32 words): double-buffered K-chunks, 256 rows/block
#define SA_STRIDE 36         // 32 + 4 pad  -> frag bank (4*qid + t4) conflict-free
#define SW_STRIDE 136        // 128 + 8 pad -> frag bank (8*t4 + qid) conflict-free
#define SA_BUF (256 * SA_STRIDE)          // 9216 words per buffer
#define SW_BUF (32 * SW_STRIDE)           // 4352 words per buffer
#define GEMM_SMEM ((2 * SA_BUF + 2 * SW_BUF) * 4)   // 108544 B

typedef unsigned long long ull;

// ---------------- scratch (static __device__ allocations; no cudaMalloc) ----
__device__ __half    g_y16[(size_t)N_NODES * 128]; // (A@W)*dinv buffer (fp16)
__device__ float     g_h[(size_t)N_NODES * 128];   // hidden buffer (tf32-prerounded)
__device__ int       g_cnt[N_NODES];               // zeroed; re-zeroed by k_fill
__device__ int       g_rowptr[N_NODES + 1];
__device__ int       g_cursor[N_NODES];
__device__ float     g_dinv[N_NODES];
__device__ int       g_csr[N_EDGES];
__device__ ull       g_scan_pkt[SCAN_BLOCKS];      // reset by k_fill
__device__ unsigned  g_w1t[128 * 128];             // tf32(rna) weight bits
__device__ unsigned  g_w2t[128 * 128];
__device__ unsigned  g_wf1t[144 * 128];

// ---------------- helpers ---------------------------------------------------
__device__ __forceinline__ unsigned to_tf32(float x) {
    unsigned r;
    asm("cvt.rna.tf32.f32 %0, %1;" : "=r"(r) : "f"(x));
    return r;
}

__device__ __forceinline__ void mma_tf32(
    float& d0, float& d1, float& d2, float& d3,
    unsigned a0, unsigned a1, unsigned a2, unsigned a3,
    unsigned b0, unsigned b1)
{
    asm("mma.sync.aligned.m16n8k8.row.col.f32.tf32.tf32.f32 "
        "{%0,%1,%2,%3}, {%4,%5,%6,%7}, {%8,%9}, {%0,%1,%2,%3};"
        : "+f"(d0), "+f"(d1), "+f"(d2), "+f"(d3)
        : "r"(a0), "r"(a1), "r"(a2), "r"(a3), "r"(b0), "r"(b1));
}

__device__ __forceinline__ void cp_async16(void* smem_dst, const void* gsrc) {
    unsigned saddr = (unsigned)__cvta_generic_to_shared(smem_dst);
    asm volatile("cp.async.ca.shared.global [%0], [%1], 16;"
                 :: "r"(saddr), "l"(gsrc));
}
__device__ __forceinline__ void cp_commit() {
    asm volatile("cp.async.commit_group;");
}
template <int N>
__device__ __forceinline__ void cp_wait() {
    asm volatile("cp.async.wait_group %0;" :: "n"(N));
}

__device__ __forceinline__ void edge_fetch(const int* __restrict__ ei, int e,
                                           int& src, int& dst, int is64) {
    if (is64) {
        src = ei[2 * e];
        dst = ei[2 * (N_EDGES + e)];
    } else {
        src = ei[e];
        dst = ei[N_EDGES + e];
    }
}

__device__ __forceinline__ int block_is64(const int* __restrict__ ei) {
    __shared__ int s_is64;
    if (threadIdx.x == 0) {
        int acc = 0;
        for (int j = 0; j < 64; j++) acc |= ei[2 * j + 1];
        s_is64 = (acc == 0) ? 1 : 0;
    }
    __syncthreads();
    return s_is64;
}

// ---------------- histogram --------------------------------------------------
__global__ void k_hist(const int* __restrict__ ei) {
    const int is64 = block_is64(ei);
    int e = blockIdx.x * blockDim.x + threadIdx.x;
    if (e < N_EDGES) {
        int src, dst;
        edge_fetch(ei, e, src, dst, is64);
        if ((unsigned)dst < N_NODES) atomicAdd(&g_cnt[dst], 1);
    }
}

// ---------------- scan (decoupled lookback) + rowptr/dinv + weight pre-cvt ---
__global__ void __launch_bounds__(1024) k_scan(
    const float* __restrict__ w1, const float* __restrict__ w2,
    const float* __restrict__ wf1)
{
    __shared__ int sm[1024];
    __shared__ int s_prefix;
    const int b = blockIdx.x;
    const int i = b * 1024 + threadIdx.x;

    // weight tf32(rna) pre-conversion (device-code writes to device symbols)
    if (i < 128 * 128) g_w1t[i] = to_tf32(w1[i]);
    if (i < 128 * 128) g_w2t[i] = to_tf32(w2[i]);
    if (i < 144 * 128) g_wf1t[i] = to_tf32(wf1[i]);

    const int v = (i < N_NODES) ? g_cnt[i] : 0;
    sm[threadIdx.x] = v;
    __syncthreads();
#pragma unroll
    for (int off = 1; off < 1024; off <<= 1) {
        int t = (threadIdx.x >= off) ? sm[threadIdx.x - off] : 0;
        __syncthreads();
        sm[threadIdx.x] += t;
        __syncthreads();
    }
    const int incl = sm[threadIdx.x];

    if (threadIdx.x == 0) {
        const int total = sm[1023];
        if (b == 0) {
            atomicExch(&g_scan_pkt[0], (2ull << 32) | (unsigned)total);
            s_prefix = 0;
        } else {
            atomicExch(&g_scan_pkt[b], (1ull << 32) | (unsigned)total);
            int pfx = 0;
            int j = b - 1;
            while (true) {
                ull w;
                do { w = *(volatile ull*)&g_scan_pkt[j]; } while ((w >> 32) == 0);
                pfx += (int)(unsigned)w;
                if ((w >> 32) == 2ull) break;
                j--;
            }
            atomicExch(&g_scan_pkt[b], (2ull << 32) | (unsigned)(pfx + total));
            s_prefix = pfx;
        }
    }
    __syncthreads();
    const int pfx = s_prefix;
    if (i < N_NODES) {
        const int rp = pfx + incl - v;
        g_rowptr[i] = rp;
        g_cursor[i] = rp;
        g_dinv[i] = rsqrtf((float)(g_cnt[i] + 1));  // +1 self-loop
    }
    if (i == 0) g_rowptr[N_NODES] = N_EDGES;
}

// ---------------- CSR fill + state reset for next replay ---------------------
__global__ void k_fill(const int* __restrict__ ei) {
    const int is64 = block_is64(ei);
    int e = blockIdx.x * blockDim.x + threadIdx.x;
    if (e < N_EDGES) {
        int src, dst;
        edge_fetch(ei, e, src, dst, is64);
        if ((unsigned)dst < N_NODES && (unsigned)src < N_NODES) {
            int pos = atomicAdd(&g_cursor[dst], 1);
            g_csr[pos] = src;
        }
    }
    if (e < N_NODES) g_cnt[e] = 0;
    if (e < SCAN_BLOCKS) g_scan_pkt[e] = 0ull;
}

// ---------------- cp.async double-buffered tf32 GEMM ------------------------
// Block: 256 rows x 128 cols, 512 threads (16 warps of 32x64 tile).
// WSEL picks the DEVICE weight scratch inside device code (host must never
// pass a __device__ symbol as an argument!).
// CVT_A=1: A raw fp32 (x), rna in loop. CVT_A=0: A = g_h (pre-rounded), raw bits.
template <int CVT_A, int WSEL>
__global__ void __launch_bounds__(512, 1) k_gemm_cp(
    const float* __restrict__ Ain)
{
    const float* __restrict__ A = CVT_A ? Ain : (const float*)g_h;
    const unsigned* __restrict__ Wt = (WSEL == 0) ? g_w1t : g_w2t;

    extern __shared__ float smem_f[];
    float* sA = smem_f;                 // [2][256][SA_STRIDE]
    float* sW = smem_f + 2 * SA_BUF;    // [2][32][SW_STRIDE]

    const int t = threadIdx.x;
    const int rb = blockIdx.x * 256;

    auto stage = [&](int chunk, int buf) {
#pragma unroll
        for (int p = 0; p < 4; p++) {
            int idx = p * 512 + t;
            int row = idx >> 3, seg = idx & 7;
            int g = rb + row; if (g >= N_NODES) g = N_NODES - 1;
            cp_async16(sA + buf * SA_BUF + row * SA_STRIDE + seg * 4,
                       A + (size_t)g * 128 + chunk * 32 + seg * 4);
        }
#pragma unroll
        for (int p = 0; p < 2; p++) {
            int idx = p * 512 + t;
            int row = idx >> 5, seg = idx & 31;
            cp_async16(sW + buf * SW_BUF + row * SW_STRIDE + seg * 4,
                       Wt + (size_t)(chunk * 32 + row) * 128 + seg * 4);
        }
        cp_commit();
    };

    const int lane = t & 31;
    const int warp = t >> 5;
    const int m0w = (warp >> 1) * 32;
    const int c0w = (warp & 1) * 64;
    const int qid = lane >> 2;
    const int t4 = lane & 3;

    float d[2][8][4];
#pragma unroll
    for (int mt = 0; mt < 2; mt++)
#pragma unroll
        for (int nt = 0; nt < 8; nt++)
#pragma unroll
            for (int i = 0; i < 4; i++) d[mt][nt][i] = 0.f;

    stage(0, 0);

#pragma unroll
    for (int c = 0; c < 4; c++) {
        if (c < 3) stage(c + 1, (c + 1) & 1);
        if (c < 3) cp_wait<1>(); else cp_wait<0>();
        __syncthreads();

        const float* cA = sA + (c & 1) * SA_BUF;
        const unsigned* cAu = (const unsigned*)cA;
        const unsigned* cW = (const unsigned*)(sW + (c & 1) * SW_BUF);
#pragma unroll
        for (int it = 0; it < 4; it++) {
            const int k = it * 8;
            unsigned a[2][4];
#pragma unroll
            for (int mt = 0; mt < 2; mt++) {
                const int base = (m0w + mt * 16 + qid) * SA_STRIDE + k + t4;
                if (CVT_A) {
                    a[mt][0] = to_tf32(cA[base]);
                    a[mt][1] = to_tf32(cA[base + 8 * SA_STRIDE]);
                    a[mt][2] = to_tf32(cA[base + 4]);
                    a[mt][3] = to_tf32(cA[base + 8 * SA_STRIDE + 4]);
                } else {
                    a[mt][0] = cAu[base];
                    a[mt][1] = cAu[base + 8 * SA_STRIDE];
                    a[mt][2] = cAu[base + 4];
                    a[mt][3] = cAu[base + 8 * SA_STRIDE + 4];
                }
            }
#pragma unroll
            for (int nt = 0; nt < 8; nt++) {
                const int wb = (k + t4) * SW_STRIDE + c0w + nt * 8 + qid;
                unsigned b0 = cW[wb];
                unsigned b1 = cW[wb + 4 * SW_STRIDE];
                mma_tf32(d[0][nt][0], d[0][nt][1], d[0][nt][2], d[0][nt][3],
                         a[0][0], a[0][1], a[0][2], a[0][3], b0, b1);
                mma_tf32(d[1][nt][0], d[1][nt][1], d[1][nt][2], d[1][nt][3],
                         a[1][0], a[1][1], a[1][2], a[1][3], b0, b1);
            }
        }
        __syncthreads();
    }

#pragma unroll
    for (int mt = 0; mt < 2; mt++) {
        const int row = rb + m0w + mt * 16 + qid;
        if (row < N_NODES) {
            const float s0 = g_dinv[row];
#pragma unroll
            for (int nt = 0; nt < 8; nt++) {
                const int col = c0w + nt * 8 + t4 * 2;
                *(__half2*)(g_y16 + (size_t)row * 128 + col) =
                    __floats2half2_rn(d[mt][nt][0] * s0, d[mt][nt][1] * s0);
            }
        }
        if (row + 8 < N_NODES) {
            const float s1 = g_dinv[row + 8];
#pragma unroll
            for (int nt = 0; nt < 8; nt++) {
                const int col = c0w + nt * 8 + t4 * 2;
                *(__half2*)(g_y16 + (size_t)(row + 8) * 128 + col) =
                    __floats2half2_rn(d[mt][nt][2] * s1, d[mt][nt][3] * s1);
            }
        }
    }
}

// ---------------- cp.async FC head ------------------------------------------
// K=144 = 4x32 chunks (g_h + g_wf1t) + 16 tail (action + g_wf1t).
// In-loop A rna-cvt (idempotent on pre-rounded g_h; needed for raw action).
__global__ void __launch_bounds__(512, 1) k_fc_cp(
    const float* __restrict__ act, const float* __restrict__ bias,
    const float* __restrict__ w2, const float* __restrict__ w2b,
    float* __restrict__ out)
{
    extern __shared__ float smem_f[];
    float* sA = smem_f;                 // [2][256][SA_STRIDE]
    float* sW = smem_f + 2 * SA_BUF;    // [2][32][SW_STRIDE]

    const int t = threadIdx.x;
    const int rb = blockIdx.x * 256;

    auto stage_main = [&](int chunk, int buf) {
#pragma unroll
        for (int p = 0; p < 4; p++) {
            int idx = p * 512 + t;
            int row = idx >> 3, seg = idx & 7;
            int g = rb + row; if (g >= N_NODES) g = N_NODES - 1;
            cp_async16(sA + buf * SA_BUF + row * SA_STRIDE + seg * 4,
                       g_h + (size_t)g * 128 + chunk * 32 + seg * 4);
        }
#pragma unroll
        for (int p = 0; p < 2; p++) {
            int idx = p * 512 + t;
            int row = idx >> 5, seg = idx & 31;
            cp_async16(sW + buf * SW_BUF + row * SW_STRIDE + seg * 4,
                       g_wf1t + (size_t)(chunk * 32 + row) * 128 + seg * 4);
        }
        cp_commit();
    };
    auto stage_tail = [&](int buf) {
#pragma unroll
        for (int p = 0; p < 2; p++) {
            int idx = p * 512 + t;
            int row = idx >> 2, seg = idx & 3;
            int g = rb + row; if (g >= N_NODES) g = N_NODES - 1;
            cp_async16(sA + buf * SA_BUF + row * SA_STRIDE + seg * 4,
                       act + (size_t)g * 16 + seg * 4);
        }
        {
            int row = t >> 5, seg = t & 31;
            cp_async16(sW + buf * SW_BUF + row * SW_STRIDE + seg * 4,
                       g_wf1t + (size_t)(128 + row) * 128 + seg * 4);
        }
        cp_commit();
    };

    const int lane = t & 31;
    const int warp = t >> 5;
    const int m0w = (warp >> 1) * 32;
    const int c0w = (warp & 1) * 64;
    const int qid = lane >> 2;
    const int t4 = lane & 3;

    float d[2][8][4];
#pragma unroll
    for (int mt = 0; mt < 2; mt++)
#pragma unroll
        for (int nt = 0; nt < 8; nt++)
#pragma unroll
            for (int i = 0; i < 4; i++) d[mt][nt][i] = 0.f;

    stage_main(0, 0);

#pragma unroll
    for (int c = 0; c < 5; c++) {
        if (c < 4) {
            if (c + 1 < 4) stage_main(c + 1, (c + 1) & 1);
            else stage_tail((c + 1) & 1);
            cp_wait<1>();
        } else {
            cp_wait<0>();
        }
        __syncthreads();

        const float* cA = sA + (c & 1) * SA_BUF;
        const unsigned* cW = (const unsigned*)(sW + (c & 1) * SW_BUF);
        const int iters = (c < 4) ? 4 : 2;
#pragma unroll
        for (int it = 0; it < 4; it++) {
            if (it >= iters) break;
            const int k = it * 8;
            unsigned a[2][4];
#pragma unroll
            for (int mt = 0; mt < 2; mt++) {
                const int base = (m0w + mt * 16 + qid) * SA_STRIDE + k + t4;
                a[mt][0] = to_tf32(cA[base]);
                a[mt][1] = to_tf32(cA[base + 8 * SA_STRIDE]);
                a[mt][2] = to_tf32(cA[base + 4]);
                a[mt][3] = to_tf32(cA[base + 8 * SA_STRIDE + 4]);
            }
#pragma unroll
            for (int nt = 0; nt < 8; nt++) {
                const int wb = (k + t4) * SW_STRIDE + c0w + nt * 8 + qid;
                unsigned b0 = cW[wb];
                unsigned b1 = cW[wb + 4 * SW_STRIDE];
                mma_tf32(d[0][nt][0], d[0][nt][1], d[0][nt][2], d[0][nt][3],
                         a[0][0], a[0][1], a[0][2], a[0][3], b0, b1);
                mma_tf32(d[1][nt][0], d[1][nt][1], d[1][nt][2], d[1][nt][3],
                         a[1][0], a[1][1], a[1][2], a[1][3], b0, b1);
            }
        }
        __syncthreads();
    }

    // epilogue: relu(+bias) . fc2 over this warp's 64 cols
    float p[2][2];
    p[0][0] = p[0][1] = p[1][0] = p[1][1] = 0.f;
#pragma unroll
    for (int mt = 0; mt < 2; mt++)
#pragma unroll
        for (int nt = 0; nt < 8; nt++) {
            const int col = c0w + nt * 8 + t4 * 2;
            float2 bv = *(const float2*)(bias + col);
            float2 wv = *(const float2*)(w2 + col);
            p[mt][0] += fmaxf(d[mt][nt][0] + bv.x, 0.f) * wv.x
                      + fmaxf(d[mt][nt][1] + bv.y, 0.f) * wv.y;
            p[mt][1] += fmaxf(d[mt][nt][2] + bv.x, 0.f) * wv.x
                      + fmaxf(d[mt][nt][3] + bv.y, 0.f) * wv.y;
        }
#pragma unroll
    for (int mt = 0; mt < 2; mt++)
#pragma unroll
        for (int h = 0; h < 2; h++) {
            p[mt][h] += __shfl_xor_sync(0xFFFFFFFFu, p[mt][h], 1);
            p[mt][h] += __shfl_xor_sync(0xFFFFFFFFu, p[mt][h], 2);
        }

    float* scr = smem_f;   // 256 floats; safe after final barrier
    if (c0w == 0 && t4 == 0) {
#pragma unroll
        for (int mt = 0; mt < 2; mt++) {
            scr[m0w + mt * 16 + qid] = p[mt][0];
            scr[m0w + mt * 16 + qid + 8] = p[mt][1];
        }
    }
    __syncthreads();
    if (c0w == 64 && t4 == 0) {
        const float ob = __ldg(w2b);
#pragma unroll
        for (int mt = 0; mt < 2; mt++) {
            int lr = m0w + mt * 16 + qid;
            int grow = rb + lr;
            if (grow < N_NODES) out[grow] = p[mt][0] + scr[lr] + ob;
            if (grow + 8 < N_NODES) out[grow + 8] = p[mt][1] + scr[lr + 8] + ob;
        }
    }
}

// ---------------- gather-aggregate: one warp per dst row (fp16 y) -----------
// Output pre-rounded to tf32(rna) — bit-identical to in-loop cvt at consumers.
__global__ void __launch_bounds__(256) k_aggregate(
    const float* __restrict__ bias)
{
    const int lane = threadIdx.x & 31;
    const int warp = threadIdx.x >> 5;
    const int row = blockIdx.x * 8 + warp;
    if (row >= N_NODES) return;

    const int s = g_rowptr[row];
    const int e = g_rowptr[row + 1];
    const uint2* yv = (const uint2*)g_y16;

    float4 a0, a1, a2, a3;
    {
        uint2 u = __ldg(&yv[(size_t)row * 32 + lane]);
        float2 f0 = __half22float2(*(__half2*)&u.x);
        float2 f1 = __half22float2(*(__half2*)&u.y);
        a0 = make_float4(f0.x, f0.y, f1.x, f1.y);
    }
    a1 = make_float4(0.f, 0.f, 0.f, 0.f);
    a2 = a1; a3 = a1;

    int i = s;
    for (; i + 4 <= e; i += 4) {
        int i0 = g_csr[i + 0];
        int i1 = g_csr[i + 1];
        int i2 = g_csr[i + 2];
        int i3 = g_csr[i + 3];
        uint2 u0 = __ldg(&yv[(size_t)i0 * 32 + lane]);
        uint2 u1 = __ldg(&yv[(size_t)i1 * 32 + lane]);
        uint2 u2 = __ldg(&yv[(size_t)i2 * 32 + lane]);
        uint2 u3 = __ldg(&yv[(size_t)i3 * 32 + lane]);
        float2 f;
        f = __half22float2(*(__half2*)&u0.x); a0.x += f.x; a0.y += f.y;
        f = __half22float2(*(__half2*)&u0.y); a0.z += f.x; a0.w += f.y;
        f = __half22float2(*(__half2*)&u1.x); a1.x += f.x; a1.y += f.y;
        f = __half22float2(*(__half2*)&u1.y); a1.z += f.x; a1.w += f.y;
        f = __half22float2(*(__half2*)&u2.x); a2.x += f.x; a2.y += f.y;
        f = __half22float2(*(__half2*)&u2.y); a2.z += f.x; a2.w += f.y;
        f = __half22float2(*(__half2*)&u3.x); a3.x += f.x; a3.y += f.y;
        f = __half22float2(*(__half2*)&u3.y); a3.z += f.x; a3.w += f.y;
    }
    for (; i < e; i++) {
        int ix = g_csr[i];
        uint2 u = __ldg(&yv[(size_t)ix * 32 + lane]);
        float2 f;
        f = __half22float2(*(__half2*)&u.x); a0.x += f.x; a0.y += f.y;
        f = __half22float2(*(__half2*)&u.y); a0.z += f.x; a0.w += f.y;
    }
    float4 a = make_float4(a0.x + a1.x + a2.x + a3.x,
                           a0.y + a1.y + a2.y + a3.y,
                           a0.z + a1.z + a2.z + a3.z,
                           a0.w + a1.w + a2.w + a3.w);

    const float dv = g_dinv[row];
    float4 b4 = __ldg((const float4*)(bias + lane * 4));
    float4 o = make_float4(
        __uint_as_float(to_tf32(fmaxf(a.x * dv + b4.x, 0.f))),
        __uint_as_float(to_tf32(fmaxf(a.y * dv + b4.y, 0.f))),
        __uint_as_float(to_tf32(fmaxf(a.z * dv + b4.z, 0.f))),
        __uint_as_float(to_tf32(fmaxf(a.w * dv + b4.w, 0.f))));
    *(float4*)(g_h + (size_t)row * 128 + lane * 4) = o;
}

// ---------------- launch ----------------------------------------------------
extern "C" void kernel_launch(void* const* d_in, const int* in_sizes, int n_in,
                              void* d_out, int out_size)
{
    const float* x      = (const float*)d_in[0];
    const int*   ei     = (const int*)d_in[1];
    const float* action = (const float*)d_in[2];
    const float* g1w    = (const float*)d_in[3];
    const float* g1b    = (const float*)d_in[4];
    const float* g2w    = (const float*)d_in[5];
    const float* g2b    = (const float*)d_in[6];
    const float* f1w    = (const float*)d_in[7];
    const float* f1b    = (const float*)d_in[8];
    const float* f2w    = (const float*)d_in[9];
    const float* f2b    = (const float*)d_in[10];
    float*       q      = (float*)d_out;

    cudaFuncSetAttribute(k_gemm_cp<1, 0>, cudaFuncAttributeMaxDynamicSharedMemorySize, GEMM_SMEM);
    cudaFuncSetAttribute(k_gemm_cp<0, 1>, cudaFuncAttributeMaxDynamicSharedMemorySize, GEMM_SMEM);
    cudaFuncSetAttribute(k_fc_cp,         cudaFuncAttributeMaxDynamicSharedMemorySize, GEMM_SMEM);

    const int agg_grid = (N_NODES + 7) / 8;

    // 8 launches; gemm1 kept at index 3 for the ncu window
    k_hist<<<(N_EDGES + 255) / 256, 256>>>(ei);                       // 0
    k_scan<<<SCAN_BLOCKS, 1024>>>(g1w, g2w, f1w);                     // 1
    k_fill<<<(N_EDGES + 255) / 256, 256>>>(ei);                       // 2
    k_gemm_cp<1, 0><<<GEMM_BLOCKS, 512, GEMM_SMEM>>>(x);              // 3  <- profiled
    k_aggregate<<<agg_grid, 256>>>(g1b);                              // 4

    k_gemm_cp<0, 1><<<GEMM_BLOCKS, 512, GEMM_SMEM>>>(nullptr);        // 5
    k_aggregate<<<agg_grid, 256>>>(g2b);                              // 6

    k_fc_cp<<<GEMM_BLOCKS, 512, GEMM_SMEM>>>(action, f1b, f2w, f2b, q);  // 7
}